// round 3
// baseline (speedup 1.0000x reference)
#include <cuda_runtime.h>

// ---------------- problem dims (fixed by the dataset) ----------------
#define BB  4
#define QQ  1024
#define DDIM 1024
#define NHD 16
#define DHD 64
#define DID 4096

// ---------------- device scratch (allocation-free rule: __device__ globals) ---
__device__ float g_heads[(size_t)BB*QQ*3*DDIM];          // [B*Q, 3072]
__device__ float g_rk  [(size_t)QQ*DDIM];                // [Q, 1024]
__device__ float g_qrw [(size_t)BB*NHD*QQ*DHD];          // [bn][i][dh], q + r_w_bias
__device__ float g_qrr [(size_t)BB*NHD*QQ*DHD];          // q + r_r_bias
__device__ float g_kh  [(size_t)BB*NHD*QQ*DHD];
__device__ float g_vh  [(size_t)BB*NHD*QQ*DHD];
__device__ float g_rkh [(size_t)NHD*QQ*DHD];             // [n][s][dh]
__device__ float g_S   [(size_t)BB*NHD*QQ*QQ];           // scores -> probs
__device__ float g_P   [(size_t)BB*NHD*QQ*QQ];           // full qrr . rk
__device__ float g_av  [(size_t)BB*QQ*DDIM];
__device__ float g_t1  [(size_t)BB*QQ*DDIM];
__device__ float g_o1  [(size_t)BB*QQ*DDIM];
__device__ float g_ffh [(size_t)BB*QQ*DID];
__device__ float g_t2  [(size_t)BB*QQ*DDIM];

// ---------------- generic fp32 SIMT GEMM --------------------------------------
// C = A * B^T (BT=true, B is [N,K] row-major)  or  C = A * B (BT=false, B is [K,N])
// A is [M,K] row-major (lda = K). Batched via blockIdx.z: z -> (zb = z/nh, zn = z%nh),
// pointer offsets = zb*s?B + zn*s?N (element strides).
// EPI: 0 = none, 1 = +bias[col], 2 = +bias[col] then ReLU.
// Requires: M % BM == 0, N % BN == 0, K % BK == 0 (true for all call sites here).
template<int BM,int BN,int BK,int TM,int TN,bool BT,int EPI>
__global__ __launch_bounds__(256) void gemm_kernel(
    const float* __restrict__ A, const float* __restrict__ Bp,
    float* __restrict__ C, const float* __restrict__ bias,
    int K, int N, int ldc,
    long saB, long saN, long sbB, long sbN, long scB, long scN, int nh)
{
    constexpr int TX  = BN/TN, TY = BM/TM;
    static_assert(TX*TY == 256, "need 256 threads");
    constexpr int TMH = TM/4, TNH = TN/4;
    __shared__ float As[BK][BM+4];
    __shared__ float Bs[BK][BN+4];

    const int tid = threadIdx.x;
    const int tx = tid % TX, ty = tid / TX;
    const int z  = blockIdx.z;
    const int zb = z / nh, zn = z % nh;
    A  += (size_t)zb*saB + (size_t)zn*saN;
    Bp += (size_t)zb*sbB + (size_t)zn*sbN;
    C  += (size_t)zb*scB + (size_t)zn*scN;
    const int m0 = blockIdx.y * BM;
    const int n0 = blockIdx.x * BN;

    float acc[TM][TN];
    #pragma unroll
    for (int i=0;i<TM;i++)
        #pragma unroll
        for (int j=0;j<TN;j++) acc[i][j]=0.f;

    for (int k0=0;k0<K;k0+=BK){
        constexpr int AV = (BM*BK/4)/256;
        #pragma unroll
        for (int it=0;it<AV;it++){
            int v   = tid + it*256;
            int row = v/(BK/4);
            int kc  = (v%(BK/4))*4;
            float4 f = *(const float4*)(A + (size_t)(m0+row)*K + (k0+kc));
            As[kc+0][row]=f.x; As[kc+1][row]=f.y; As[kc+2][row]=f.z; As[kc+3][row]=f.w;
        }
        constexpr int BV = (BN*BK/4)/256;
        if constexpr (BT){
            #pragma unroll
            for (int it=0;it<BV;it++){
                int v   = tid + it*256;
                int row = v/(BK/4);
                int kc  = (v%(BK/4))*4;
                float4 f = *(const float4*)(Bp + (size_t)(n0+row)*K + (k0+kc));
                Bs[kc+0][row]=f.x; Bs[kc+1][row]=f.y; Bs[kc+2][row]=f.z; Bs[kc+3][row]=f.w;
            }
        } else {
            #pragma unroll
            for (int it=0;it<BV;it++){
                int v  = tid + it*256;
                int kk = v/(BN/4);
                int nc = (v%(BN/4))*4;
                *(float4*)&Bs[kk][nc] = *(const float4*)(Bp + (size_t)(k0+kk)*N + (n0+nc));
            }
        }
        __syncthreads();
        #pragma unroll
        for (int k=0;k<BK;k++){
            float a[TM], b[TN];
            #pragma unroll
            for (int h=0;h<TMH;h++){
                float4 f = *(const float4*)&As[k][h*TY*4 + ty*4];
                a[h*4+0]=f.x; a[h*4+1]=f.y; a[h*4+2]=f.z; a[h*4+3]=f.w;
            }
            #pragma unroll
            for (int h=0;h<TNH;h++){
                float4 f = *(const float4*)&Bs[k][h*TX*4 + tx*4];
                b[h*4+0]=f.x; b[h*4+1]=f.y; b[h*4+2]=f.z; b[h*4+3]=f.w;
            }
            #pragma unroll
            for (int i=0;i<TM;i++)
                #pragma unroll
                for (int j=0;j<TN;j++)
                    acc[i][j] += a[i]*b[j];
        }
        __syncthreads();
    }

    #pragma unroll
    for (int i=0;i<TM;i++){
        int row = m0 + (i/4)*TY*4 + ty*4 + (i%4);
        #pragma unroll
        for (int h=0;h<TNH;h++){
            int col = n0 + h*TX*4 + tx*4;
            float4 v = make_float4(acc[i][h*4+0],acc[i][h*4+1],acc[i][h*4+2],acc[i][h*4+3]);
            if constexpr (EPI>=1){
                float4 bb = *(const float4*)(bias + col);
                v.x+=bb.x; v.y+=bb.y; v.z+=bb.z; v.w+=bb.w;
            }
            if constexpr (EPI==2){
                v.x=fmaxf(v.x,0.f); v.y=fmaxf(v.y,0.f); v.z=fmaxf(v.z,0.f); v.w=fmaxf(v.w,0.f);
            }
            *(float4*)(C + (size_t)row*ldc + col) = v;
        }
    }
}

// ---------------- reorg: heads -> per-head contiguous q(+biases)/k/v ----------
__global__ void reorg_qkv_kernel(const float4* __restrict__ heads,
                                 const float4* __restrict__ rwb,
                                 const float4* __restrict__ rrb,
                                 float4* __restrict__ qrw, float4* __restrict__ qrr,
                                 float4* __restrict__ kh,  float4* __restrict__ vh)
{
    int idx = blockIdx.x*256 + threadIdx.x;        // < B*Q*NH*DH/4 = 1048576
    int dh4 = idx & 15;
    int n   = (idx >> 4) & 15;
    int i   = (idx >> 8) & 1023;
    int b   = idx >> 18;
    size_t hb = ((size_t)(b*QQ + i))*768 + n*16 + dh4;   // heads row = 3072 floats = 768 f4
    float4 q4 = heads[hb];
    float4 k4 = heads[hb + 256];
    float4 v4 = heads[hb + 512];
    float4 rw = rwb[n*16 + dh4];
    float4 rr = rrb[n*16 + dh4];
    size_t o = ((size_t)((b*NHD + n)*QQ + i))*16 + dh4;
    qrw[o] = make_float4(q4.x+rw.x, q4.y+rw.y, q4.z+rw.z, q4.w+rw.w);
    qrr[o] = make_float4(q4.x+rr.x, q4.y+rr.y, q4.z+rr.z, q4.w+rr.w);
    kh[o]  = k4;
    vh[o]  = v4;
}

__global__ void reorg_rk_kernel(const float4* __restrict__ rk, float4* __restrict__ rkh)
{
    int idx = blockIdx.x*256 + threadIdx.x;        // < Q*NH*DH/4 = 262144
    int dh4 = idx & 15;
    int n   = (idx >> 4) & 15;
    int s   = idx >> 8;
    rkh[((size_t)(n*QQ + s))*16 + dh4] = rk[(size_t)s*256 + n*16 + dh4];
}

// ---------------- masked softmax with rel-shift gather ------------------------
// score[i][j] = (AC[i][j] + P[i][Q-1-i+j]) / 8  for j <= i; softmax over j<=i;
// writes prob back into S (zeros for j > i so AV can be a plain GEMM).
__global__ void softmax_kernel(float* __restrict__ S, const float* __restrict__ P)
{
    const int Q = QQ;
    int i = blockIdx.x, bn = blockIdx.y, tid = threadIdx.x;
    float* srow = S + ((size_t)bn*Q + i)*Q;
    const float* prow = P + ((size_t)bn*Q + i)*Q + (Q-1-i);
    int len = i+1;
    __shared__ float buf[QQ];
    __shared__ float red[8];
    int wid = tid>>5, lane = tid&31;

    float m = -1e30f;
    for (int j=tid; j<len; j+=256){
        float s = (srow[j] + prow[j]) * 0.125f;
        buf[j] = s;
        m = fmaxf(m, s);
    }
    #pragma unroll
    for (int o=16;o;o>>=1) m = fmaxf(m, __shfl_xor_sync(0xffffffffu,m,o));
    if (!lane) red[wid] = m;
    __syncthreads();
    m = red[0];
    #pragma unroll
    for (int t=1;t<8;t++) m = fmaxf(m, red[t]);
    __syncthreads();

    float l = 0.f;
    for (int j=tid; j<len; j+=256) l += __expf(buf[j]-m);
    #pragma unroll
    for (int o=16;o;o>>=1) l += __shfl_xor_sync(0xffffffffu,l,o);
    if (!lane) red[wid] = l;
    __syncthreads();
    l = 0.f;
    #pragma unroll
    for (int t=0;t<8;t++) l += red[t];
    float inv = 1.f/l;

    for (int j=tid; j<Q; j+=256)
        srow[j] = (j<len) ? __expf(buf[j]-m)*inv : 0.f;
}

// ---------------- fused residual-add + LayerNorm ------------------------------
__global__ void add_ln_kernel(const float* __restrict__ X, const float* __restrict__ Y,
                              const float* __restrict__ gam, const float* __restrict__ bet,
                              float* __restrict__ out)
{
    int row = blockIdx.x, tid = threadIdx.x;
    const float4* X4 = (const float4*)X + (size_t)row*256;
    const float4* Y4 = (const float4*)Y + (size_t)row*256;
    float4 x = X4[tid], y = Y4[tid];
    x.x += y.x; x.y += y.y; x.z += y.z; x.w += y.w;
    float s  = x.x + x.y + x.z + x.w;
    float s2 = x.x*x.x + x.y*x.y + x.z*x.z + x.w*x.w;
    __shared__ float red[16];
    #pragma unroll
    for (int o=16;o;o>>=1){
        s  += __shfl_xor_sync(0xffffffffu,s ,o);
        s2 += __shfl_xor_sync(0xffffffffu,s2,o);
    }
    int wid = tid>>5, lane = tid&31;
    if (!lane){ red[wid]=s; red[8+wid]=s2; }
    __syncthreads();
    s=0.f; s2=0.f;
    #pragma unroll
    for (int t=0;t<8;t++){ s += red[t]; s2 += red[8+t]; }
    float mean = s  * (1.f/1024.f);
    float var  = s2 * (1.f/1024.f) - mean*mean;
    float rstd = rsqrtf(var + 1e-5f);
    float4 g = ((const float4*)gam)[tid];
    float4 b = ((const float4*)bet)[tid];
    float4 o;
    o.x = (x.x-mean)*rstd*g.x + b.x;
    o.y = (x.y-mean)*rstd*g.y + b.y;
    o.z = (x.z-mean)*rstd*g.z + b.z;
    o.w = (x.w-mean)*rstd*g.w + b.w;
    ((float4*)out)[(size_t)row*256 + tid] = o;
}

// ---------------- launch ------------------------------------------------------
extern "C" void kernel_launch(void* const* d_in, const int* in_sizes, int n_in,
                              void* d_out, int out_size)
{
    (void)in_sizes; (void)n_in; (void)out_size;
    const float* w        = (const float*)d_in[0];
    const float* r        = (const float*)d_in[1];
    // d_in[2] = attention_mask (causal triu) — structure known, unused
    const float* qkv_w    = (const float*)d_in[3];
    const float* r_w      = (const float*)d_in[4];
    const float* o_w      = (const float*)d_in[5];
    const float* r_w_bias = (const float*)d_in[6];
    const float* r_r_bias = (const float*)d_in[7];
    const float* ln1_g    = (const float*)d_in[8];
    const float* ln1_b    = (const float*)d_in[9];
    const float* ff_w1    = (const float*)d_in[10];
    const float* ff_b1    = (const float*)d_in[11];
    const float* ff_w2    = (const float*)d_in[12];
    const float* ff_b2    = (const float*)d_in[13];
    const float* ln2_g    = (const float*)d_in[14];
    const float* ln2_b    = (const float*)d_in[15];
    float* out = (float*)d_out;

    float *heads,*rk,*qrw,*qrr,*kh,*vh,*rkh,*S,*P,*av,*t1,*o1,*ffh,*t2;
    cudaGetSymbolAddress((void**)&heads, g_heads);
    cudaGetSymbolAddress((void**)&rk,    g_rk);
    cudaGetSymbolAddress((void**)&qrw,   g_qrw);
    cudaGetSymbolAddress((void**)&qrr,   g_qrr);
    cudaGetSymbolAddress((void**)&kh,    g_kh);
    cudaGetSymbolAddress((void**)&vh,    g_vh);
    cudaGetSymbolAddress((void**)&rkh,   g_rkh);
    cudaGetSymbolAddress((void**)&S,     g_S);
    cudaGetSymbolAddress((void**)&P,     g_P);
    cudaGetSymbolAddress((void**)&av,    g_av);
    cudaGetSymbolAddress((void**)&t1,    g_t1);
    cudaGetSymbolAddress((void**)&o1,    g_o1);
    cudaGetSymbolAddress((void**)&ffh,   g_ffh);
    cudaGetSymbolAddress((void**)&t2,    g_t2);

    const dim3 thr(256);
    const long SQ  = (long)QQ*QQ;        // 1048576
    const long SHD = (long)QQ*DHD;       // 65536

    // 1) heads = w @ qkv_w^T : [4096,1024] x [3072,1024]^T
    gemm_kernel<128,128,16,8,8,true,0><<<dim3(3072/128,4096/128,1),thr>>>(
        w, qkv_w, heads, nullptr, 1024, 3072, 3072, 0,0,0,0,0,0, 1);

    // 2) rk = r @ r_w^T : [1024,1024]
    gemm_kernel<128,128,16,8,8,true,0><<<dim3(8,8,1),thr>>>(
        r, r_w, rk, nullptr, 1024, 1024, 1024, 0,0,0,0,0,0, 1);

    // 3) reorg into per-head contiguous layout (+ biases folded into q)
    reorg_qkv_kernel<<<4096,256>>>((const float4*)heads,(const float4*)r_w_bias,
                                   (const float4*)r_r_bias,
                                   (float4*)qrw,(float4*)qrr,(float4*)kh,(float4*)vh);
    reorg_rk_kernel<<<1024,256>>>((const float4*)rk,(float4*)rkh);

    // 4) AC[bn] = QRW[bn] @ K[bn]^T : batched [1024,1024,K=64]
    gemm_kernel<128,128,16,8,8,true,0><<<dim3(8,8,BB*NHD),thr>>>(
        qrw, kh, S, nullptr, 64, 1024, 1024,
        16*SHD, SHD, 16*SHD, SHD, 16*SQ, SQ, NHD);

    // 5) P[bn] = QRR[bn] @ RK[n]^T : batched [1024,1024,K=64]
    gemm_kernel<128,128,16,8,8,true,0><<<dim3(8,8,BB*NHD),thr>>>(
        qrr, rkh, P, nullptr, 64, 1024, 1024,
        16*SHD, SHD, 0, SHD, 16*SQ, SQ, NHD);

    // 6) masked softmax with rel-shift gather; prob written into S (zeros above diag)
    softmax_kernel<<<dim3(QQ, BB*NHD),256>>>(S, P);

    // 7) AV[bn] = prob[bn] @ V[bn] : [1024,64,K=1024], scattered into [B*Q,1024]
    gemm_kernel<128,64,16,8,4,false,0><<<dim3(1,8,BB*NHD),thr>>>(
        S, vh, av, nullptr, 1024, 64, 1024,
        16*SQ, SQ, 16*SHD, SHD, (long)QQ*DDIM, 64, NHD);

    // 8) o-proj = av @ o_w^T : [4096,1024,1024]
    gemm_kernel<128,128,16,8,8,true,0><<<dim3(8,32,1),thr>>>(
        av, o_w, t1, nullptr, 1024, 1024, 1024, 0,0,0,0,0,0, 1);

    // 9) out1 = LN(w + o-proj)
    add_ln_kernel<<<4096,256>>>(w, t1, ln1_g, ln1_b, o1);

    // 10) ffh = relu(out1 @ ff_w1^T + b1) : [4096,4096,1024]
    gemm_kernel<128,128,16,8,8,true,2><<<dim3(32,32,1),thr>>>(
        o1, ff_w1, ffh, ff_b1, 1024, 4096, 4096, 0,0,0,0,0,0, 1);

    // 11) ff = ffh @ ff_w2^T + b2 : [4096,1024,4096]
    gemm_kernel<128,128,16,8,8,true,1><<<dim3(8,32,1),thr>>>(
        ffh, ff_w2, t2, ff_b2, 4096, 1024, 1024, 0,0,0,0,0,0, 1);

    // 12) out = LN(out1 + ff)
    add_ln_kernel<<<4096,256>>>(o1, t2, ln2_g, ln2_b, out);
}

// round 9
// speedup vs baseline: 1.2946x; 1.2946x over previous
#include <cuda_runtime.h>
#include <cuda_bf16.h>
#include <cstdint>

// ---------------- problem dims (fixed by the dataset) ----------------
#define BB  4
#define QQ  1024
#define DDIM 1024
#define NHD 16
#define DHD 64
#define DID 4096

// ---------------- fp32 scratch ------------------------------------------------
__device__ float g_heads[(size_t)BB*QQ*3*DDIM];          // [B*Q, 3072]
__device__ float g_rk  [(size_t)QQ*DDIM];                // [Q, 1024]
__device__ float g_vh  [(size_t)BB*NHD*QQ*DHD];          // [bn][j][64] fp32 (SIMT AV)
__device__ float g_S   [(size_t)BB*NHD*QQ*QQ];           // scores -> probs
__device__ float g_P   [(size_t)BB*NHD*QQ*QQ];           // full qrr . rk
__device__ float g_av  [(size_t)BB*QQ*DDIM];
__device__ float g_t1  [(size_t)BB*QQ*DDIM];
__device__ float g_o1  [(size_t)BB*QQ*DDIM];
__device__ float g_ffh [(size_t)BB*QQ*DID];
__device__ float g_t2  [(size_t)BB*QQ*DDIM];

// ---------------- bf16 split scratch (K' = 3K layout) -------------------------
__device__ __nv_bfloat16 g_wsA  [(size_t)BB*QQ*3*DDIM];      // w split (A: hi,hi,lo)
__device__ __nv_bfloat16 g_qkvwB[(size_t)3*DDIM*3*DDIM];     // qkv_w split (B: hi,lo,hi)
__device__ __nv_bfloat16 g_rsA  [(size_t)QQ*3*DDIM];
__device__ __nv_bfloat16 g_rwB  [(size_t)DDIM*3*DDIM];
__device__ __nv_bfloat16 g_owB  [(size_t)DDIM*3*DDIM];
__device__ __nv_bfloat16 g_w1B  [(size_t)DID*3*DDIM];
__device__ __nv_bfloat16 g_w2B  [(size_t)DDIM*3*DID];
__device__ __nv_bfloat16 g_qrwA [(size_t)BB*NHD*QQ*3*DHD];
__device__ __nv_bfloat16 g_qrrA [(size_t)BB*NHD*QQ*3*DHD];
__device__ __nv_bfloat16 g_khB  [(size_t)BB*NHD*QQ*3*DHD];
__device__ __nv_bfloat16 g_rkhB [(size_t)NHD*QQ*3*DHD];
__device__ __nv_bfloat16 g_avA  [(size_t)BB*QQ*3*DDIM];
__device__ __nv_bfloat16 g_o1A  [(size_t)BB*QQ*3*DDIM];
__device__ __nv_bfloat16 g_ffhA [(size_t)BB*QQ*3*DID];

// =============================================================================
// helpers (family-agnostic PTX only: cp.async, ldmatrix, mma.sync)
// =============================================================================
static __device__ __forceinline__ uint32_t s2u(const void* p){
    uint32_t a;
    asm("{ .reg .u64 t; cvta.to.shared.u64 t, %1; cvt.u32.u64 %0, t; }" : "=r"(a) : "l"(p));
    return a;
}
static __device__ __forceinline__ void cp16(uint32_t dst, const void* src){
    asm volatile("cp.async.cg.shared.global [%0], [%1], 16;" :: "r"(dst), "l"(src));
}
static __device__ __forceinline__ void ldsm4(uint32_t* r, uint32_t a){
    asm volatile("ldmatrix.sync.aligned.m8n8.x4.shared.b16 {%0,%1,%2,%3}, [%4];"
        : "=r"(r[0]),"=r"(r[1]),"=r"(r[2]),"=r"(r[3]) : "r"(a));
}
static __device__ __forceinline__ void mma16816(float* d, const uint32_t* a, const uint32_t* b){
    asm volatile("mma.sync.aligned.m16n8k16.row.col.f32.bf16.bf16.f32 "
        "{%0,%1,%2,%3}, {%4,%5,%6,%7}, {%8,%9}, {%0,%1,%2,%3};"
        : "+f"(d[0]),"+f"(d[1]),"+f"(d[2]),"+f"(d[3])
        : "r"(a[0]),"r"(a[1]),"r"(a[2]),"r"(a[3]), "r"(b[0]),"r"(b[1]));
}

// Tile smem layout: rows of 32 bf16 (64B = 4 chunks of 16B); two rows share a
// 128B line; chunk-within-line = ((row&1)*4 + kc) ^ ((row>>1)&7).
// Gives conflict-free ldmatrix phases AND conflict-free cp.async fills.
static __device__ __forceinline__ uint32_t tadr(int row, int kc){
    return (uint32_t)(((row>>1)<<7) + (((((row&1)<<2) + kc) ^ ((row>>1)&7))<<4));
}

// =============================================================================
// mma.sync bf16 GEMM: C[M,N] = A'[M,K'] * B'[N,K']^T, fp32 accum.
// 128x128 block, BK=32, 8 warps (warp tile 32m x 64n), cp.async double buffer.
// EPI: 0 none, 1 +bias[col], 2 +bias+ReLU. Batched via blockIdx.z like before.
// =============================================================================
#define TILEB 8192   // one 128x32 bf16 tile in bytes

template<int EPI>
__global__ __launch_bounds__(256) void mma_gemm(
    const __nv_bfloat16* __restrict__ Ag, const __nv_bfloat16* __restrict__ Bg,
    float* __restrict__ C, const float* __restrict__ bias,
    int Kp, int ldc,
    long saB, long saN, long sbB, long sbN, long scB, long scN, int nh)
{
    __shared__ __align__(1024) __nv_bfloat16 sm[2][2][128*32]; // [buf][A|B][tile]
    const uint32_t sbase = s2u(sm);
    const int tid = threadIdx.x, lane = tid & 31, wid = tid >> 5;
    const int wm = wid >> 1, wn = wid & 1;

    const int z = blockIdx.z, zb = z / nh, zn = z % nh;
    Ag += (size_t)zb*saB + (size_t)zn*saN;
    Bg += (size_t)zb*sbB + (size_t)zn*sbN;
    C  += (size_t)zb*scB + (size_t)zn*scN;
    const int m0 = blockIdx.y * 128;
    const int n0 = blockIdx.x * 128;
    const long strideAB = (long)Kp * 2;   // row stride in bytes

    // precomputed ldmatrix offsets within a tile
    uint32_t aoff[2][2], boff[4][2];
    {
        const int r15 = lane & 15, hA = lane >> 4;         // A: rows 0..15, col-half
        #pragma unroll
        for (int mt=0; mt<2; mt++){
            int row = wm*32 + mt*16 + r15;
            #pragma unroll
            for (int kk=0; kk<2; kk++)
                aoff[mt][kk] = tadr(row, 2*kk + hA);
        }
        const int rb = lane & 7, g = lane >> 3;            // B: g: tile=(g>>1), half=g&1
        #pragma unroll
        for (int nt2=0; nt2<4; nt2++){
            int row = wn*64 + nt2*16 + ((g>>1)<<3) + rb;
            #pragma unroll
            for (int kk=0; kk<2; kk++)
                boff[nt2][kk] = tadr(row, 2*kk + (g&1));
        }
    }

    float acc[2][8][4];
    #pragma unroll
    for (int mt=0; mt<2; mt++)
        #pragma unroll
        for (int nt=0; nt<8; nt++)
            #pragma unroll
            for (int q=0; q<4; q++) acc[mt][nt][q] = 0.f;

    const int crow = tid >> 2, ckc = tid & 3;  // cp.async chunk coords

    auto load = [&](int c, int st){
        const char* As = (const char*)Ag + (long)(c*32 + ckc*8)*2;
        const char* Bs = (const char*)Bg + (long)(c*32 + ckc*8)*2;
        const uint32_t ab = sbase + (uint32_t)st*(2*TILEB);
        const uint32_t bb = ab + TILEB;
        #pragma unroll
        for (int it=0; it<2; it++){
            int row = crow + it*64;
            int grA = m0 + row, grB = n0 + row;
            uint32_t o = tadr(row, ckc);
            cp16(ab + o, As + (long)grA*strideAB);
            cp16(bb + o, Bs + (long)grB*strideAB);
        }
        asm volatile("cp.async.commit_group;");
    };

    const int nc = Kp >> 5;
    load(0, 0);
    for (int c=0; c<nc; c++){
        if (c+1 < nc){
            load(c+1, (c+1)&1);
            asm volatile("cp.async.wait_group 1;");
        } else {
            asm volatile("cp.async.wait_group 0;");
        }
        __syncthreads();
        const uint32_t ab = sbase + (uint32_t)(c&1)*(2*TILEB);
        const uint32_t bb = ab + TILEB;
        #pragma unroll
        for (int kk=0; kk<2; kk++){
            uint32_t a[2][4], b[4][4];
            ldsm4(a[0], ab + aoff[0][kk]);
            ldsm4(a[1], ab + aoff[1][kk]);
            #pragma unroll
            for (int nt2=0; nt2<4; nt2++) ldsm4(b[nt2], bb + boff[nt2][kk]);
            #pragma unroll
            for (int mt=0; mt<2; mt++)
                #pragma unroll
                for (int nt=0; nt<8; nt++)
                    mma16816(acc[mt][nt], a[mt], &b[nt>>1][(nt&1)*2]);
        }
        __syncthreads();
    }

    // epilogue
    const int row0 = m0 + wm*32 + (lane>>2);
    const int col0 = n0 + wn*64 + (lane&3)*2;
    #pragma unroll
    for (int mt=0; mt<2; mt++){
        #pragma unroll
        for (int nt=0; nt<8; nt++){
            int cN = col0 + nt*8;
            float2 b2 = make_float2(0.f, 0.f);
            if (EPI >= 1) b2 = *(const float2*)(bias + cN);
            float2 v0 = make_float2(acc[mt][nt][0] + b2.x, acc[mt][nt][1] + b2.y);
            float2 v1 = make_float2(acc[mt][nt][2] + b2.x, acc[mt][nt][3] + b2.y);
            if (EPI == 2){
                v0.x = fmaxf(v0.x, 0.f); v0.y = fmaxf(v0.y, 0.f);
                v1.x = fmaxf(v1.x, 0.f); v1.y = fmaxf(v1.y, 0.f);
            }
            int r = row0 + mt*16;
            *(float2*)(C + (size_t)r*ldc + cN)     = v0;
            *(float2*)(C + (size_t)(r+8)*ldc + cN) = v1;
        }
    }
}

// =============================================================================
// bf16 double-split helpers
// =============================================================================
static __device__ __forceinline__ void split4(float4 x, uint2& h, uint2& l){
    __nv_bfloat162 h0 = __floats2bfloat162_rn(x.x, x.y);
    __nv_bfloat162 h1 = __floats2bfloat162_rn(x.z, x.w);
    float r0 = x.x - __bfloat162float(__low2bfloat16(h0));
    float r1 = x.y - __bfloat162float(__high2bfloat16(h0));
    float r2 = x.z - __bfloat162float(__low2bfloat16(h1));
    float r3 = x.w - __bfloat162float(__high2bfloat16(h1));
    __nv_bfloat162 l0 = __floats2bfloat162_rn(r0, r1);
    __nv_bfloat162 l1 = __floats2bfloat162_rn(r2, r3);
    h.x = *reinterpret_cast<unsigned*>(&h0); h.y = *reinterpret_cast<unsigned*>(&h1);
    l.x = *reinterpret_cast<unsigned*>(&l0); l.y = *reinterpret_cast<unsigned*>(&l1);
}

// X [rows,K] fp32 -> Y [rows,3K] bf16.  BSIDE=false: [hi,hi,lo]; true: [hi,lo,hi]
template<bool BSIDE>
__global__ void split_kernel(const float4* __restrict__ X, __nv_bfloat16* __restrict__ Y,
                             int Kq, long total4)
{
    long i = (long)blockIdx.x*256 + threadIdx.x;
    if (i >= total4) return;
    long r = i / Kq;
    int  c = (int)(i % Kq) * 4;
    int  K = Kq * 4;
    uint2 h, l;
    split4(X[i], h, l);
    __nv_bfloat16* yr = Y + r*(3L*K) + c;
    *(uint2*)yr         = h;
    *(uint2*)(yr +   K) = BSIDE ? l : h;
    *(uint2*)(yr + 2*K) = BSIDE ? h : l;
}

// ---------------- reorg: heads -> per-head split q(+biases)/k, fp32 v ---------
__global__ void reorg_qkv_kernel(const float4* __restrict__ heads,
                                 const float4* __restrict__ rwb,
                                 const float4* __restrict__ rrb,
                                 __nv_bfloat16* __restrict__ qrwA,
                                 __nv_bfloat16* __restrict__ qrrA,
                                 __nv_bfloat16* __restrict__ khB,
                                 float4* __restrict__ vh)
{
    int idx = blockIdx.x*256 + threadIdx.x;        // < B*Q*NH*DH/4 = 1048576
    int dh4 = idx & 15;
    int n   = (idx >> 4) & 15;
    int i   = (idx >> 8) & 1023;
    int b   = idx >> 18;
    size_t hb = ((size_t)(b*QQ + i))*768 + n*16 + dh4;
    float4 q4 = heads[hb];
    float4 k4 = heads[hb + 256];
    float4 v4 = heads[hb + 512];
    float4 rw = rwb[n*16 + dh4];
    float4 rr = rrb[n*16 + dh4];
    size_t bn = (size_t)(b*NHD + n);
    vh[(bn*QQ + i)*16 + dh4] = v4;
    size_t rb = (bn*QQ + i)*192 + dh4*4;
    uint2 h, l;
    float4 xw = make_float4(q4.x+rw.x, q4.y+rw.y, q4.z+rw.z, q4.w+rw.w);
    split4(xw, h, l);
    *(uint2*)(qrwA + rb) = h; *(uint2*)(qrwA + rb + 64) = h; *(uint2*)(qrwA + rb + 128) = l;
    float4 xr = make_float4(q4.x+rr.x, q4.y+rr.y, q4.z+rr.z, q4.w+rr.w);
    split4(xr, h, l);
    *(uint2*)(qrrA + rb) = h; *(uint2*)(qrrA + rb + 64) = h; *(uint2*)(qrrA + rb + 128) = l;
    split4(k4, h, l);
    *(uint2*)(khB + rb) = h;  *(uint2*)(khB + rb + 64) = l;  *(uint2*)(khB + rb + 128) = h;
}

__global__ void reorg_rk_kernel(const float4* __restrict__ rk, __nv_bfloat16* __restrict__ rkhB)
{
    int idx = blockIdx.x*256 + threadIdx.x;        // < Q*NH*DH/4 = 262144
    int dh4 = idx & 15;
    int n   = (idx >> 4) & 15;
    int s   = idx >> 8;
    float4 x = rk[(size_t)s*256 + n*16 + dh4];
    uint2 h, l;
    split4(x, h, l);
    size_t rb = ((size_t)(n*QQ + s))*192 + dh4*4;
    *(uint2*)(rkhB + rb) = h; *(uint2*)(rkhB + rb + 64) = l; *(uint2*)(rkhB + rb + 128) = h;
}

// =============================================================================
// SIMT fp32 GEMM (for AV: prob @ V, with causal K-limit)
// =============================================================================
template<int BM,int BN,int BKc,int TM,int TN,bool BT,int EPI,bool CAUSAL>
__global__ __launch_bounds__(256) void gemm_kernel(
    const float* __restrict__ A, const float* __restrict__ Bp,
    float* __restrict__ C, const float* __restrict__ bias,
    int K, int N, int ldc,
    long saB, long saN, long sbB, long sbN, long scB, long scN, int nh)
{
    constexpr int TX  = BN/TN, TY = BM/TM;
    static_assert(TX*TY == 256, "need 256 threads");
    constexpr int TNH = TN/4, TMH = TM/4;
    __shared__ float As[BKc][BM+4];
    __shared__ float Bs[BKc][BN+4];

    const int tid = threadIdx.x;
    const int tx = tid % TX, ty = tid / TX;
    const int z  = blockIdx.z;
    const int zb = z / nh, zn = z % nh;
    A  += (size_t)zb*saB + (size_t)zn*saN;
    Bp += (size_t)zb*sbB + (size_t)zn*sbN;
    C  += (size_t)zb*scB + (size_t)zn*scN;
    const int m0 = blockIdx.y * BM;
    const int n0 = blockIdx.x * BN;
    const int kend = CAUSAL ? (m0 + BM) : K;

    float acc[TM][TN];
    #pragma unroll
    for (int i=0;i<TM;i++)
        #pragma unroll
        for (int j=0;j<TN;j++) acc[i][j]=0.f;

    for (int k0=0;k0<kend;k0+=BKc){
        constexpr int AV = (BM*BKc/4)/256;
        #pragma unroll
        for (int it=0;it<AV;it++){
            int v   = tid + it*256;
            int row = v/(BKc/4);
            int kc  = (v%(BKc/4))*4;
            float4 f = *(const float4*)(A + (size_t)(m0+row)*K + (k0+kc));
            As[kc+0][row]=f.x; As[kc+1][row]=f.y; As[kc+2][row]=f.z; As[kc+3][row]=f.w;
        }
        constexpr int BV = (BN*BKc/4)/256;
        if constexpr (BT){
            #pragma unroll
            for (int it=0;it<BV;it++){
                int v   = tid + it*256;
                int row = v/(BKc/4);
                int kc  = (v%(BKc/4))*4;
                float4 f = *(const float4*)(Bp + (size_t)(n0+row)*K + (k0+kc));
                Bs[kc+0][row]=f.x; Bs[kc+1][row]=f.y; Bs[kc+2][row]=f.z; Bs[kc+3][row]=f.w;
            }
        } else {
            #pragma unroll
            for (int it=0;it<BV;it++){
                int v  = tid + it*256;
                int kk = v/(BN/4);
                int nc = (v%(BN/4))*4;
                *(float4*)&Bs[kk][nc] = *(const float4*)(Bp + (size_t)(k0+kk)*N + (n0+nc));
            }
        }
        __syncthreads();
        #pragma unroll
        for (int k=0;k<BKc;k++){
            float a[TM], b[TN];
            #pragma unroll
            for (int h=0;h<TMH;h++){
                float4 f = *(const float4*)&As[k][h*TY*4 + ty*4];
                a[h*4+0]=f.x; a[h*4+1]=f.y; a[h*4+2]=f.z; a[h*4+3]=f.w;
            }
            #pragma unroll
            for (int h=0;h<TNH;h++){
                float4 f = *(const float4*)&Bs[k][h*TX*4 + tx*4];
                b[h*4+0]=f.x; b[h*4+1]=f.y; b[h*4+2]=f.z; b[h*4+3]=f.w;
            }
            #pragma unroll
            for (int i=0;i<TM;i++)
                #pragma unroll
                for (int j=0;j<TN;j++)
                    acc[i][j] += a[i]*b[j];
        }
        __syncthreads();
    }

    #pragma unroll
    for (int i=0;i<TM;i++){
        int row = m0 + (i/4)*TY*4 + ty*4 + (i%4);
        #pragma unroll
        for (int h=0;h<TNH;h++){
            int col = n0 + h*TX*4 + tx*4;
            float4 v = make_float4(acc[i][h*4+0],acc[i][h*4+1],acc[i][h*4+2],acc[i][h*4+3]);
            if constexpr (EPI>=1){
                float4 bb = *(const float4*)(bias + col);
                v.x+=bb.x; v.y+=bb.y; v.z+=bb.z; v.w+=bb.w;
            }
            if constexpr (EPI==2){
                v.x=fmaxf(v.x,0.f); v.y=fmaxf(v.y,0.f); v.z=fmaxf(v.z,0.f); v.w=fmaxf(v.w,0.f);
            }
            *(float4*)(C + (size_t)row*ldc + col) = v;
        }
    }
}

// ---------------- masked softmax with rel-shift gather ------------------------
__global__ void softmax_kernel(float* __restrict__ S, const float* __restrict__ P)
{
    const int Q = QQ;
    int i = blockIdx.x, bn = blockIdx.y, tid = threadIdx.x;
    float* srow = S + ((size_t)bn*Q + i)*Q;
    const float* prow = P + ((size_t)bn*Q + i)*Q + (Q-1-i);
    int len = i+1;
    int blkend = (i & ~127) + 128;   // AV only reads j < blkend for this row
    __shared__ float buf[QQ];
    __shared__ float red[8];
    int wid = tid>>5, lane = tid&31;

    float m = -1e30f;
    for (int j=tid; j<len; j+=256){
        float s = (srow[j] + prow[j]) * 0.125f;
        buf[j] = s;
        m = fmaxf(m, s);
    }
    #pragma unroll
    for (int o=16;o;o>>=1) m = fmaxf(m, __shfl_xor_sync(0xffffffffu,m,o));
    if (!lane) red[wid] = m;
    __syncthreads();
    m = red[0];
    #pragma unroll
    for (int t=1;t<8;t++) m = fmaxf(m, red[t]);
    __syncthreads();

    float l = 0.f;
    for (int j=tid; j<len; j+=256) l += __expf(buf[j]-m);
    #pragma unroll
    for (int o=16;o;o>>=1) l += __shfl_xor_sync(0xffffffffu,l,o);
    if (!lane) red[wid] = l;
    __syncthreads();
    l = 0.f;
    #pragma unroll
    for (int t=0;t<8;t++) l += red[t];
    float inv = 1.f/l;

    for (int j=tid; j<blkend; j+=256)
        srow[j] = (j<len) ? __expf(buf[j]-m)*inv : 0.f;
}

// ---------------- fused residual-add + LayerNorm ------------------------------
__global__ void add_ln_kernel(const float* __restrict__ X, const float* __restrict__ Y,
                              const float* __restrict__ gam, const float* __restrict__ bet,
                              float* __restrict__ out)
{
    int row = blockIdx.x, tid = threadIdx.x;
    const float4* X4 = (const float4*)X + (size_t)row*256;
    const float4* Y4 = (const float4*)Y + (size_t)row*256;
    float4 x = X4[tid], y = Y4[tid];
    x.x += y.x; x.y += y.y; x.z += y.z; x.w += y.w;
    float s  = x.x + x.y + x.z + x.w;
    float s2 = x.x*x.x + x.y*x.y + x.z*x.z + x.w*x.w;
    __shared__ float red[16];
    #pragma unroll
    for (int o=16;o;o>>=1){
        s  += __shfl_xor_sync(0xffffffffu,s ,o);
        s2 += __shfl_xor_sync(0xffffffffu,s2,o);
    }
    int wid = tid>>5, lane = tid&31;
    if (!lane){ red[wid]=s; red[8+wid]=s2; }
    __syncthreads();
    s=0.f; s2=0.f;
    #pragma unroll
    for (int t=0;t<8;t++){ s += red[t]; s2 += red[8+t]; }
    float mean = s  * (1.f/1024.f);
    float var  = s2 * (1.f/1024.f) - mean*mean;
    float rstd = rsqrtf(var + 1e-5f);
    float4 g = ((const float4*)gam)[tid];
    float4 b = ((const float4*)bet)[tid];
    float4 o;
    o.x = (x.x-mean)*rstd*g.x + b.x;
    o.y = (x.y-mean)*rstd*g.y + b.y;
    o.z = (x.z-mean)*rstd*g.z + b.z;
    o.w = (x.w-mean)*rstd*g.w + b.w;
    ((float4*)out)[(size_t)row*256 + tid] = o;
}

// ---------------- launch ------------------------------------------------------
extern "C" void kernel_launch(void* const* d_in, const int* in_sizes, int n_in,
                              void* d_out, int out_size)
{
    (void)in_sizes; (void)n_in; (void)out_size;
    const float* w        = (const float*)d_in[0];
    const float* r        = (const float*)d_in[1];
    const float* qkv_w    = (const float*)d_in[3];
    const float* r_w      = (const float*)d_in[4];
    const float* o_w      = (const float*)d_in[5];
    const float* r_w_bias = (const float*)d_in[6];
    const float* r_r_bias = (const float*)d_in[7];
    const float* ln1_g    = (const float*)d_in[8];
    const float* ln1_b    = (const float*)d_in[9];
    const float* ff_w1    = (const float*)d_in[10];
    const float* ff_b1    = (const float*)d_in[11];
    const float* ff_w2    = (const float*)d_in[12];
    const float* ff_b2    = (const float*)d_in[13];
    const float* ln2_g    = (const float*)d_in[14];
    const float* ln2_b    = (const float*)d_in[15];
    float* out = (float*)d_out;

    float *heads,*rk,*vh,*S,*P,*av,*t1,*o1,*ffh,*t2;
    __nv_bfloat16 *wsA,*qkvwB,*rsA,*rwB,*owB,*w1B,*w2B,*qrwA,*qrrA,*khB,*rkhB,*avA,*o1A,*ffhA;
    cudaGetSymbolAddress((void**)&heads, g_heads);
    cudaGetSymbolAddress((void**)&rk,    g_rk);
    cudaGetSymbolAddress((void**)&vh,    g_vh);
    cudaGetSymbolAddress((void**)&S,     g_S);
    cudaGetSymbolAddress((void**)&P,     g_P);
    cudaGetSymbolAddress((void**)&av,    g_av);
    cudaGetSymbolAddress((void**)&t1,    g_t1);
    cudaGetSymbolAddress((void**)&o1,    g_o1);
    cudaGetSymbolAddress((void**)&ffh,   g_ffh);
    cudaGetSymbolAddress((void**)&t2,    g_t2);
    cudaGetSymbolAddress((void**)&wsA,   g_wsA);
    cudaGetSymbolAddress((void**)&qkvwB, g_qkvwB);
    cudaGetSymbolAddress((void**)&rsA,   g_rsA);
    cudaGetSymbolAddress((void**)&rwB,   g_rwB);
    cudaGetSymbolAddress((void**)&owB,   g_owB);
    cudaGetSymbolAddress((void**)&w1B,   g_w1B);
    cudaGetSymbolAddress((void**)&w2B,   g_w2B);
    cudaGetSymbolAddress((void**)&qrwA,  g_qrwA);
    cudaGetSymbolAddress((void**)&qrrA,  g_qrrA);
    cudaGetSymbolAddress((void**)&khB,   g_khB);
    cudaGetSymbolAddress((void**)&rkhB,  g_rkhB);
    cudaGetSymbolAddress((void**)&avA,   g_avA);
    cudaGetSymbolAddress((void**)&o1A,   g_o1A);
    cudaGetSymbolAddress((void**)&ffhA,  g_ffhA);

    const dim3 thr(256);
    const long SQ   = (long)QQ*QQ;          // 1048576
    const long SH3  = (long)QQ*3*DHD;       // 196608 (per-bn split stride)

    // ---- split inputs ----
    split_kernel<false><<<4096,  256>>>((const float4*)w,     wsA,   256, (long)4096*256);
    split_kernel<true ><<<3072,  256>>>((const float4*)qkv_w, qkvwB, 256, (long)3072*256);
    split_kernel<false><<<1024,  256>>>((const float4*)r,     rsA,   256, (long)1024*256);
    split_kernel<true ><<<1024,  256>>>((const float4*)r_w,   rwB,   256, (long)1024*256);
    split_kernel<true ><<<1024,  256>>>((const float4*)o_w,   owB,   256, (long)1024*256);
    split_kernel<true ><<<4096,  256>>>((const float4*)ff_w1, w1B,   256, (long)4096*256);
    split_kernel<true ><<<4096,  256>>>((const float4*)ff_w2, w2B,  1024, (long)1024*1024);

    // 1) heads = w @ qkv_w^T : [4096,3072], K'=3072
    mma_gemm<0><<<dim3(24,32,1), thr>>>(
        wsA, qkvwB, heads, nullptr, 3072, 3072, 0,0,0,0,0,0, 1);

    // 2) rk = r @ r_w^T : [1024,1024], K'=3072
    mma_gemm<0><<<dim3(8,8,1), thr>>>(
        rsA, rwB, rk, nullptr, 3072, 1024, 0,0,0,0,0,0, 1);

    // 3) reorg + split per-head operands
    reorg_qkv_kernel<<<4096,256>>>((const float4*)heads,(const float4*)r_w_bias,
                                   (const float4*)r_r_bias, qrwA, qrrA, khB, (float4*)vh);
    reorg_rk_kernel<<<1024,256>>>((const float4*)rk, rkhB);

    // 4) AC[bn] = QRW[bn] @ K[bn]^T : [1024,1024], K'=192, batched z=64
    mma_gemm<0><<<dim3(8,8,BB*NHD), thr>>>(
        qrwA, khB, S, nullptr, 192, 1024,
        SH3, 0, SH3, 0, SQ, 0, 1);

    // 5) P[bn] = QRR[bn] @ RK[n]^T : B shared across batch (nh=16)
    mma_gemm<0><<<dim3(8,8,BB*NHD), thr>>>(
        qrrA, rkhB, P, nullptr, 192, 1024,
        16*SH3, SH3, 0, SH3, 16*SQ, SQ, NHD);

    // 6) masked softmax with rel-shift gather
    softmax_kernel<<<dim3(QQ, BB*NHD),256>>>(S, P);

    // 7) AV[bn] = prob[bn] @ V[bn] (SIMT fp32, causal K-limit)
    gemm_kernel<128,64,16,8,4,false,0,true><<<dim3(1,8,BB*NHD),thr>>>(
        S, vh, av, nullptr, 1024, 64, 1024,
        16*SQ, SQ, 16*((long)QQ*DHD), (long)QQ*DHD, (long)QQ*DDIM, 64, NHD);

    // 8) o-proj = av @ o_w^T : [4096,1024], K'=3072
    split_kernel<false><<<4096,256>>>((const float4*)av, avA, 256, (long)4096*256);
    mma_gemm<0><<<dim3(8,32,1), thr>>>(
        avA, owB, t1, nullptr, 3072, 1024, 0,0,0,0,0,0, 1);

    // 9) out1 = LN(w + o-proj)
    add_ln_kernel<<<4096,256>>>(w, t1, ln1_g, ln1_b, o1);

    // 10) ffh = relu(out1 @ ff_w1^T + b1) : [4096,4096], K'=3072
    split_kernel<false><<<4096,256>>>((const float4*)o1, o1A, 256, (long)4096*256);
    mma_gemm<2><<<dim3(32,32,1), thr>>>(
        o1A, w1B, ffh, ff_b1, 3072, 4096, 0,0,0,0,0,0, 1);

    // 11) ff = ffh @ ff_w2^T + b2 : [4096,1024], K'=12288
    split_kernel<false><<<16384,256>>>((const float4*)ffh, ffhA, 1024, (long)4096*1024);
    mma_gemm<1><<<dim3(8,32,1), thr>>>(
        ffhA, w2B, t2, ff_b2, 12288, 1024, 0,0,0,0,0,0, 1);

    // 12) out = LN(out1 + ff)
    add_ln_kernel<<<4096,256>>>(o1, t2, ln2_g, ln2_b, out);
}